// round 13
// baseline (speedup 1.0000x reference)
#include <cuda_runtime.h>
#include <cuda_bf16.h>
#include <cstdint>

// Problem dims
#define Bq   8
#define Nq   8192
#define Sq   2048
#define D1q  128
#define D2q  256
#define KIN  384          // D1 + D2
#define C1   256          // layer-1 out channels
#define C2   128          // layer-2 out channels
#define MROWS (Bq * Nq)   // 65536

// ---------------------------------------------------------------------------
// Scratch (device globals — no allocation allowed)
// ---------------------------------------------------------------------------
__device__ __align__(16) __nv_bfloat16 g_xh[(size_t)MROWS * KIN];  // bf16 hi (reused [M][256] for GEMM2 A)
__device__ __align__(16) __nv_bfloat16 g_xl[(size_t)MROWS * KIN];  // bf16 lo
__device__ __align__(16) float g_y1 [(size_t)MROWS * C1];          // linear1 out fp32
__device__ __align__(16) float g_y2 [(size_t)MROWS * C2];          // linear2 out fp32
__device__ __align__(16) float g_f2t[(size_t)Bq * Sq * D2q];       // points2 transposed
__device__ int   g_idx[(size_t)Bq * Nq * 3];
__device__ float g_wts[(size_t)Bq * Nq * 3];
__device__ float g_part[128 * 2 * C1];
__device__ float g_scale1[C1], g_shift1[C1];
__device__ float g_scale2[C2], g_shift2[C2];
__device__ __align__(16) __nv_bfloat16 g_w1h[C1 * KIN], g_w1l[C1 * KIN];
__device__ __align__(16) __nv_bfloat16 g_w2h[C2 * C1],  g_w2l[C2 * C1];

// ---------------------------------------------------------------------------
// PTX helpers — ONLY family-portable instructions (sm_80+): cp.async,
// ldmatrix, mma.sync. No tcgen05 anywhere (ptxas here targets plain sm_103).
// ---------------------------------------------------------------------------
__device__ __forceinline__ uint32_t smem_u32(const void* p) {
    uint32_t a;
    asm("{ .reg .u64 t; cvta.to.shared.u64 t, %1; cvt.u32.u64 %0, t; }"
        : "=r"(a) : "l"(p));
    return a;
}
__device__ __forceinline__ void cp16(uint32_t s, const void* g) {
    asm volatile("cp.async.cg.shared.global [%0], [%1], 16;" :: "r"(s), "l"(g) : "memory");
}
__device__ __forceinline__ void cp_commit() {
    asm volatile("cp.async.commit_group;" ::: "memory");
}
template <int N> __device__ __forceinline__ void cp_wait() {
    asm volatile("cp.async.wait_group %0;" :: "n"(N) : "memory");
}
#define LDMX4(r, addr) \
    asm volatile("ldmatrix.sync.aligned.m8n8.x4.shared.b16 {%0,%1,%2,%3}, [%4];" \
        : "=r"((r)[0]), "=r"((r)[1]), "=r"((r)[2]), "=r"((r)[3]) : "r"(addr))

__device__ __forceinline__ void mma16816(float* d, const uint32_t* a,
                                         uint32_t b0, uint32_t b1) {
    asm volatile(
        "mma.sync.aligned.m16n8k16.row.col.f32.bf16.bf16.f32 "
        "{%0,%1,%2,%3}, {%4,%5,%6,%7}, {%8,%9}, {%0,%1,%2,%3};"
        : "+f"(d[0]), "+f"(d[1]), "+f"(d[2]), "+f"(d[3])
        : "r"(a[0]), "r"(a[1]), "r"(a[2]), "r"(a[3]), "r"(b0), "r"(b1));
}

__device__ __forceinline__ void bf16_split(float v, __nv_bfloat16& h, __nv_bfloat16& l) {
    h = __float2bfloat16(v);
    l = __float2bfloat16(v - __bfloat162float(h));
}

// ---------------------------------------------------------------------------
// Weight pre-split: fp32 -> bf16 hi/lo
// ---------------------------------------------------------------------------
__global__ void conv_w_kernel(const float* __restrict__ w1, const float* __restrict__ w2) {
    int i = blockIdx.x * 256 + threadIdx.x;
    if (i < C1 * KIN) {
        __nv_bfloat16 h, l; bf16_split(w1[i], h, l);
        g_w1h[i] = h; g_w1l[i] = l;
    }
    if (i < C2 * C1) {
        __nv_bfloat16 h, l; bf16_split(w2[i], h, l);
        g_w2h[i] = h; g_w2l[i] = l;
    }
}

// ---------------------------------------------------------------------------
// Transpose points2 [B, D2, S] -> g_f2t [B, S, D2]
// ---------------------------------------------------------------------------
__global__ void transpose_p2_kernel(const float* __restrict__ p2) {
    __shared__ float tile[32][33];
    int b  = blockIdx.z;
    int s0 = blockIdx.x * 32, d0 = blockIdx.y * 32;
    int tx = threadIdx.x, ty = threadIdx.y;
    const float* src = p2 + (size_t)b * D2q * Sq;
    #pragma unroll
    for (int i = ty; i < 32; i += 8)
        tile[i][tx] = src[(size_t)(d0 + i) * Sq + s0 + tx];
    __syncthreads();
    float* dst = g_f2t + (size_t)b * Sq * D2q;
    #pragma unroll
    for (int i = ty; i < 32; i += 8)
        dst[(size_t)(s0 + i) * D2q + d0 + tx] = tile[tx][i];
}

// ---------------------------------------------------------------------------
// Transpose points1 [B, D1, N] -> g_xh/g_xl columns [0, 128)
// ---------------------------------------------------------------------------
__global__ void transpose_p1_kernel(const float* __restrict__ p1) {
    __shared__ float tile[32][33];
    int b  = blockIdx.z;
    int n0 = blockIdx.x * 32, d0 = blockIdx.y * 32;
    int tx = threadIdx.x, ty = threadIdx.y;
    const float* src = p1 + (size_t)b * D1q * Nq;
    #pragma unroll
    for (int i = ty; i < 32; i += 8)
        tile[i][tx] = src[(size_t)(d0 + i) * Nq + n0 + tx];
    __syncthreads();
    #pragma unroll
    for (int i = ty; i < 32; i += 8) {
        float v = tile[tx][i];
        __nv_bfloat16 h, l; bf16_split(v, h, l);
        size_t o = ((size_t)b * Nq + n0 + i) * KIN + d0 + tx;
        g_xh[o] = h; g_xl[o] = l;
    }
}

// ---------------------------------------------------------------------------
// 3-NN + weights. 256 threads = 128 point-PAIRS x 2 half-scans of S.
// Each thread scans 1024 candidates for TWO query points -> each LDS.128 is
// reused twice. Distance folded to 3 FMAs via precomputed (-2px,-2py,-2pz):
//   d' = fmaf(m2x,cx, fmaf(m2y,cy, fmaf(m2z,cz, |c|^2)))  (= d_true - |q|^2,
// a per-query constant shift, so ordering is unchanged; |q|^2 re-added at the
// end). Strict-< insertion preserves reference tie semantics; half-1 indices
// are always larger so the merge keeps the earlier index on ties.
// ---------------------------------------------------------------------------
__global__ __launch_bounds__(256) void knn_kernel(const float* __restrict__ xyz1,
                                                  const float* __restrict__ xyz2) {
    __shared__ float4 sp[Sq];            // 32 KB
    __shared__ float  sd[6 * 128];       // half-1 results: 2 points x 3 dists
    __shared__ int    si[6 * 128];
    int b = blockIdx.y;
    const float* x2 = xyz2 + (size_t)b * 3 * Sq;
    for (int s = threadIdx.x; s < Sq; s += 256) {
        float xx = x2[s], yy = x2[Sq + s], zz = x2[2 * Sq + s];
        float4 c = { xx, yy, zz, fmaf(xx, xx, fmaf(yy, yy, zz * zz)) };
        sp[s] = c;
    }
    __syncthreads();

    const int half = threadIdx.x >> 7;          // 0 or 1
    const int pr   = threadIdx.x & 127;         // pair id within block
    const int n0q  = blockIdx.x * 256 + pr * 2; // first of the 2 query points
    const float* x1 = xyz1 + (size_t)b * 3 * Nq;
    const float pxA = x1[n0q],     pyA = x1[Nq + n0q],     pzA = x1[2 * Nq + n0q];
    const float pxB = x1[n0q + 1], pyB = x1[Nq + n0q + 1], pzB = x1[2 * Nq + n0q + 1];
    const float m2xA = -2.0f * pxA, m2yA = -2.0f * pyA, m2zA = -2.0f * pzA;
    const float m2xB = -2.0f * pxB, m2yB = -2.0f * pyB, m2zB = -2.0f * pzB;

    float a0 = 3.4e38f, a1 = 3.4e38f, a2 = 3.4e38f;
    float b0 = 3.4e38f, b1 = 3.4e38f, b2 = 3.4e38f;
    int   ai0 = 0, ai1 = 0, ai2 = 0, bi0 = 0, bi1 = 0, bi2 = 0;

    const int s0 = half * (Sq / 2);
    #pragma unroll 4
    for (int s = s0; s < s0 + Sq / 2; s++) {
        float4 c = sp[s];
        float dA = fmaf(m2xA, c.x, fmaf(m2yA, c.y, fmaf(m2zA, c.z, c.w)));
        float dB = fmaf(m2xB, c.x, fmaf(m2yB, c.y, fmaf(m2zB, c.z, c.w)));
        if (dA < a2) {
            if (dA < a1) {
                a2 = a1; ai2 = ai1;
                if (dA < a0) { a1 = a0; ai1 = ai0; a0 = dA; ai0 = s; }
                else         { a1 = dA; ai1 = s; }
            } else { a2 = dA; ai2 = s; }
        }
        if (dB < b2) {
            if (dB < b1) {
                b2 = b1; bi2 = bi1;
                if (dB < b0) { b1 = b0; bi1 = bi0; b0 = dB; bi0 = s; }
                else         { b1 = dB; bi1 = s; }
            } else { b2 = dB; bi2 = s; }
        }
    }

    if (half == 1) {
        sd[pr] = a0; sd[128 + pr] = a1; sd[256 + pr] = a2;
        sd[384 + pr] = b0; sd[512 + pr] = b1; sd[640 + pr] = b2;
        si[pr] = ai0; si[128 + pr] = ai1; si[256 + pr] = ai2;
        si[384 + pr] = bi0; si[512 + pr] = bi1; si[640 + pr] = bi2;
    }
    __syncthreads();
    if (half == 0) {
        #pragma unroll
        for (int j = 0; j < 3; j++) {
            float d = sd[j * 128 + pr];
            int  ix = si[j * 128 + pr];
            if (d < a2) {
                if (d < a1) {
                    a2 = a1; ai2 = ai1;
                    if (d < a0) { a1 = a0; ai1 = ai0; a0 = d; ai0 = ix; }
                    else        { a1 = d;  ai1 = ix; }
                } else { a2 = d; ai2 = ix; }
            }
        }
        #pragma unroll
        for (int j = 0; j < 3; j++) {
            float d = sd[(3 + j) * 128 + pr];
            int  ix = si[(3 + j) * 128 + pr];
            if (d < b2) {
                if (d < b1) {
                    b2 = b1; bi2 = bi1;
                    if (d < b0) { b1 = b0; bi1 = bi0; b0 = d; bi0 = ix; }
                    else        { b1 = d;  bi1 = ix; }
                } else { b2 = d; bi2 = ix; }
            }
        }
        float nA = fmaf(pxA, pxA, fmaf(pyA, pyA, pzA * pzA));
        float nB = fmaf(pxB, pxB, fmaf(pyB, pyB, pzB * pzB));
        a0 = fmaxf(a0 + nA, 1e-10f); a1 = fmaxf(a1 + nA, 1e-10f); a2 = fmaxf(a2 + nA, 1e-10f);
        b0 = fmaxf(b0 + nB, 1e-10f); b1 = fmaxf(b1 + nB, 1e-10f); b2 = fmaxf(b2 + nB, 1e-10f);
        {
            float w0 = 1.0f / a0, w1 = 1.0f / a1, w2 = 1.0f / a2;
            float inv = 1.0f / (w0 + w1 + w2);
            size_t base = ((size_t)b * Nq + n0q) * 3;
            g_idx[base] = ai0; g_idx[base + 1] = ai1; g_idx[base + 2] = ai2;
            g_wts[base] = w0 * inv; g_wts[base + 1] = w1 * inv; g_wts[base + 2] = w2 * inv;
        }
        {
            float w0 = 1.0f / b0, w1 = 1.0f / b1, w2 = 1.0f / b2;
            float inv = 1.0f / (w0 + w1 + w2);
            size_t base = ((size_t)b * Nq + n0q + 1) * 3;
            g_idx[base] = bi0; g_idx[base + 1] = bi1; g_idx[base + 2] = bi2;
            g_wts[base] = w0 * inv; g_wts[base + 1] = w1 * inv; g_wts[base + 2] = w2 * inv;
        }
    }
}

// ---------------------------------------------------------------------------
// Interpolate -> g_xh/g_xl columns [128, 384). 64 threads per point, float4.
// ---------------------------------------------------------------------------
__global__ void interp_kernel() {
    int b  = blockIdx.y;
    int pt = blockIdx.x * 4 + (threadIdx.x >> 6);
    int t  = threadIdx.x & 63;
    size_t qb = (size_t)b * Nq + pt;
    const int*   ip = g_idx + qb * 3;
    const float* wp = g_wts + qb * 3;
    const float* f  = g_f2t + (size_t)b * Sq * D2q;
    int d = t * 4;
    float4 f0 = *(const float4*)(f + (size_t)ip[0] * D2q + d);
    float4 f1 = *(const float4*)(f + (size_t)ip[1] * D2q + d);
    float4 f2 = *(const float4*)(f + (size_t)ip[2] * D2q + d);
    float w0 = wp[0], w1 = wp[1], w2 = wp[2];
    float a0 = fmaf(w2, f2.x, fmaf(w1, f1.x, w0 * f0.x));
    float a1 = fmaf(w2, f2.y, fmaf(w1, f1.y, w0 * f0.y));
    float a2 = fmaf(w2, f2.z, fmaf(w1, f1.z, w0 * f0.z));
    float a3 = fmaf(w2, f2.w, fmaf(w1, f1.w, w0 * f0.w));
    __nv_bfloat16 h0, l0, h1, l1, h2, l2, h3, l3;
    bf16_split(a0, h0, l0); bf16_split(a1, h1, l1);
    bf16_split(a2, h2, l2); bf16_split(a3, h3, l3);
    uint32_t ph0 = ((uint32_t)__bfloat16_as_ushort(h1) << 16) | __bfloat16_as_ushort(h0);
    uint32_t ph1 = ((uint32_t)__bfloat16_as_ushort(h3) << 16) | __bfloat16_as_ushort(h2);
    uint32_t pl0 = ((uint32_t)__bfloat16_as_ushort(l1) << 16) | __bfloat16_as_ushort(l0);
    uint32_t pl1 = ((uint32_t)__bfloat16_as_ushort(l3) << 16) | __bfloat16_as_ushort(l2);
    uint2 vh = {ph0, ph1}, vl = {pl0, pl1};
    size_t o = qb * KIN + D1q + d;
    *(uint2*)(g_xh + o) = vh;
    *(uint2*)(g_xl + o) = vl;
}

// ---------------------------------------------------------------------------
// HMMA GEMM (mma.sync m16n8k16 bf16 -> f32), 3-pass hi/lo split.
// Block 128x128, 8 warps (4 M x 2 N), warp tile 32x64, K-chunk 32,
// cp.async double buffer, 80B-padded SMEM rows (conflict-free ldmatrix).
// WHICH=1: y1[M,256] = x[M,384] @ w1^T     (A=g_xh/g_xl LDA=384)
// WHICH=2: y2[M,128] = a2[M,256] @ w2^T    (A=reused g_xh/g_xl LDA=256)
// ---------------------------------------------------------------------------
template <int WHICH>
__global__ __launch_bounds__(256) void gemm_hmma() {
    constexpr int LDA = (WHICH == 1) ? KIN : C1;
    constexpr int LDB = (WHICH == 1) ? KIN : C1;
    constexpr int KD  = (WHICH == 1) ? KIN : C1;
    constexpr int LDC = (WHICH == 1) ? C1  : C2;
    constexpr int KC  = KD / 32;
    constexpr int NITER = 3 * KC;

    const __nv_bfloat16* Ah = g_xh;
    const __nv_bfloat16* Al = g_xl;
    const __nv_bfloat16* Bh = (WHICH == 1) ? g_w1h : g_w2h;
    const __nv_bfloat16* Bl = (WHICH == 1) ? g_w1l : g_w2l;
    float* Cout = (WHICH == 1) ? g_y1 : g_y2;

    __shared__ __align__(16) char smA[2][128 * 80];
    __shared__ __align__(16) char smB[2][128 * 80];

    const int tid = threadIdx.x, lane = tid & 31, wid = tid >> 5;
    const int warp_m = wid & 3, warp_n = wid >> 2;
    const size_t row0 = (size_t)blockIdx.y * 128;
    const int col0 = blockIdx.x * 128;

    const uint32_t sAu[2] = { smem_u32(smA[0]), smem_u32(smA[1]) };
    const uint32_t sBu[2] = { smem_u32(smB[0]), smem_u32(smB[1]) };

    // ldmatrix per-lane base offsets (bytes)
    const uint32_t a_off = (uint32_t)((warp_m * 32 + ((lane >> 3) & 1) * 8 + (lane & 7)) * 80
                                      + (lane >> 4) * 16);
    const uint32_t b_off = (uint32_t)((warp_n * 64 + (lane >> 4) * 8 + (lane & 7)) * 80
                                      + ((lane >> 3) & 1) * 16);

    float acc[2][8][4] = {};

    auto issue = [&](int it, int buf) {
        const int p  = it / KC;
        const int k0 = (it - p * KC) * 32;
        const char* As = (const char*)((p == 1) ? Al : Ah);
        const char* Bs = (const char*)((p == 2) ? Bl : Bh);
        #pragma unroll
        for (int i = 0; i < 2; i++) {
            int c = tid + i * 256;
            int r = c >> 2, cc = c & 3;
            cp16(sAu[buf] + r * 80 + cc * 16,
                 As + ((row0 + r) * LDA + k0) * 2 + cc * 16);
            cp16(sBu[buf] + r * 80 + cc * 16,
                 Bs + ((size_t)(col0 + r) * LDB + k0) * 2 + cc * 16);
        }
        cp_commit();
    };

    issue(0, 0);
    for (int it = 0; it < NITER; it++) {
        const int buf = it & 1;
        if (it + 1 < NITER) { issue(it + 1, buf ^ 1); cp_wait<1>(); }
        else                { cp_wait<0>(); }
        __syncthreads();

        #pragma unroll
        for (int ks = 0; ks < 2; ks++) {
            uint32_t af[2][4];
            LDMX4(af[0], sAu[buf] + a_off + ks * 32);
            LDMX4(af[1], sAu[buf] + a_off + 16 * 80 + ks * 32);
            uint32_t bfr[4][4];
            #pragma unroll
            for (int jp = 0; jp < 4; jp++)
                LDMX4(bfr[jp], sBu[buf] + b_off + jp * 16 * 80 + ks * 32);
            #pragma unroll
            for (int mt = 0; mt < 2; mt++)
                #pragma unroll
                for (int j = 0; j < 8; j++)
                    mma16816(acc[mt][j], af[mt],
                             bfr[j >> 1][(j & 1) * 2], bfr[j >> 1][(j & 1) * 2 + 1]);
        }
        __syncthreads();
    }

    // Store: c0,c1 -> (row, col..col+1); c2,c3 -> (row+8, ...)
    #pragma unroll
    for (int mt = 0; mt < 2; mt++) {
        #pragma unroll
        for (int j = 0; j < 8; j++) {
            size_t row = row0 + warp_m * 32 + mt * 16 + (lane >> 2);
            int    col = col0 + warp_n * 64 + j * 8 + 2 * (lane & 3);
            float* p0 = Cout + row * LDC + col;
            float2 v0 = { acc[mt][j][0], acc[mt][j][1] };
            float2 v1 = { acc[mt][j][2], acc[mt][j][3] };
            *(float2*)p0 = v0;
            *(float2*)(p0 + 8 * LDC) = v1;
        }
    }
}

// ---------------------------------------------------------------------------
// BN stats (two deterministic stages)
// ---------------------------------------------------------------------------
__global__ void stats_stage1_kernel(int layer) {
    int C = layer ? C2 : C1;
    const float* Y = layer ? g_y2 : g_y1;
    int ch = threadIdx.x;
    size_t r0 = (size_t)blockIdx.x * 512;
    float s = 0.0f, sq = 0.0f;
    for (int r = 0; r < 512; r++) {
        float v = Y[(r0 + r) * C + ch];
        s += v;
        sq = fmaf(v, v, sq);
    }
    g_part[blockIdx.x * 2 * C + ch]     = s;
    g_part[blockIdx.x * 2 * C + C + ch] = sq;
}

__global__ void stats_stage2_kernel(int layer, const float* __restrict__ g,
                                    const float* __restrict__ be) {
    int C  = layer ? C2 : C1;
    int ch = threadIdx.x;
    float s = 0.0f, sq = 0.0f;
    for (int bk = 0; bk < 128; bk++) {
        s  += g_part[bk * 2 * C + ch];
        sq += g_part[bk * 2 * C + C + ch];
    }
    const float invM = 1.0f / (float)MROWS;
    float mean = s * invM;
    float var  = fmaf(sq, invM, -mean * mean);
    float scv  = g[ch] * rsqrtf(var + 1e-5f);
    float shv  = fmaf(-mean, scv, be[ch]);
    if (layer) { g_scale2[ch] = scv; g_shift2[ch] = shv; }
    else       { g_scale1[ch] = scv; g_shift1[ch] = shv; }
}

// ---------------------------------------------------------------------------
// BN+ReLU+bf16-split of y1 -> g_xh/g_xl reused as [M][256] (GEMM2 A operand)
// ---------------------------------------------------------------------------
__global__ void bnrelu_split_kernel() {
    size_t i = ((size_t)blockIdx.x * 256 + threadIdx.x) * 4;  // over MROWS*C1
    float4 v = *(const float4*)(g_y1 + i);
    int ch = (int)(i & (C1 - 1));
    float a0 = fmaxf(fmaf(v.x, g_scale1[ch],     g_shift1[ch]),     0.0f);
    float a1 = fmaxf(fmaf(v.y, g_scale1[ch + 1], g_shift1[ch + 1]), 0.0f);
    float a2 = fmaxf(fmaf(v.z, g_scale1[ch + 2], g_shift1[ch + 2]), 0.0f);
    float a3 = fmaxf(fmaf(v.w, g_scale1[ch + 3], g_shift1[ch + 3]), 0.0f);
    __nv_bfloat16 h0, l0, h1, l1, h2, l2, h3, l3;
    bf16_split(a0, h0, l0); bf16_split(a1, h1, l1);
    bf16_split(a2, h2, l2); bf16_split(a3, h3, l3);
    uint32_t ph0 = ((uint32_t)__bfloat16_as_ushort(h1) << 16) | __bfloat16_as_ushort(h0);
    uint32_t ph1 = ((uint32_t)__bfloat16_as_ushort(h3) << 16) | __bfloat16_as_ushort(h2);
    uint32_t pl0 = ((uint32_t)__bfloat16_as_ushort(l1) << 16) | __bfloat16_as_ushort(l0);
    uint32_t pl1 = ((uint32_t)__bfloat16_as_ushort(l3) << 16) | __bfloat16_as_ushort(l2);
    uint2 vh = {ph0, ph1}, vl = {pl0, pl1};
    *(uint2*)(g_xh + i) = vh;
    *(uint2*)(g_xl + i) = vl;
}

// ---------------------------------------------------------------------------
// Final epilogue: out[b, c, n] = relu(bn2(y2)), transposed write
// ---------------------------------------------------------------------------
__global__ void epilogue_kernel(float* __restrict__ out) {
    __shared__ float tile[32][33];
    int b  = blockIdx.z;
    int n0 = blockIdx.x * 32, c0 = blockIdx.y * 32;
    int tx = threadIdx.x, ty = threadIdx.y;
    #pragma unroll
    for (int i = ty; i < 32; i += 8) {
        float v = g_y2[((size_t)b * Nq + n0 + i) * C2 + c0 + tx];
        tile[i][tx] = fmaxf(fmaf(v, g_scale2[c0 + tx], g_shift2[c0 + tx]), 0.0f);
    }
    __syncthreads();
    #pragma unroll
    for (int i = ty; i < 32; i += 8)
        out[(size_t)b * C2 * Nq + (size_t)(c0 + i) * Nq + n0 + tx] = tile[tx][i];
}

// ---------------------------------------------------------------------------
// Launch
// ---------------------------------------------------------------------------
extern "C" void kernel_launch(void* const* d_in, const int* in_sizes, int n_in,
                              void* d_out, int out_size) {
    const float* xyz1    = (const float*)d_in[0];
    const float* xyz2    = (const float*)d_in[1];
    const float* points1 = (const float*)d_in[2];
    const float* points2 = (const float*)d_in[3];
    const float* w1      = (const float*)d_in[4];
    const float* g1      = (const float*)d_in[6];
    const float* be1     = (const float*)d_in[7];
    const float* w2      = (const float*)d_in[8];
    const float* g2      = (const float*)d_in[10];
    const float* be2     = (const float*)d_in[11];
    float* out = (float*)d_out;

    dim3 tb(32, 8);
    conv_w_kernel<<<(C1 * KIN + 255) / 256, 256>>>(w1, w2);
    transpose_p2_kernel<<<dim3(Sq / 32, D2q / 32, Bq), tb>>>(points2);
    transpose_p1_kernel<<<dim3(Nq / 32, D1q / 32, Bq), tb>>>(points1);
    knn_kernel<<<dim3(Nq / 256, Bq), 256>>>(xyz1, xyz2);
    interp_kernel<<<dim3(Nq / 4, Bq), 256>>>();
    gemm_hmma<1><<<dim3(C1 / 128, MROWS / 128), 256>>>();
    stats_stage1_kernel<<<128, C1>>>(0);
    stats_stage2_kernel<<<1, C1>>>(0, g1, be1);
    bnrelu_split_kernel<<<(MROWS * C1 / 4) / 256, 256>>>();
    gemm_hmma<2><<<dim3(C2 / 128, MROWS / 128), 256>>>();
    stats_stage1_kernel<<<128, C2>>>(1);
    stats_stage2_kernel<<<1, C2>>>(1, g2, be2);
    epilogue_kernel<<<dim3(Nq / 32, C2 / 32, Bq), tb>>>(out);
}